// round 10
// baseline (speedup 1.0000x reference)
#include <cuda_runtime.h>
#include <math.h>

// Problem capacities (runtime sizes from in_sizes)
#define MAXF 2000000
#define MAXV 500000

// Scratch (allocation-free rule: __device__ globals)
__device__ float4 g_fun[MAXF];    // .x = nom, .y = den, .z = tmp, .w unused
__device__ float4 g_varp[MAXV];   // ef=+1: {w*ev, w, +dl, 0},  w = e^{c p},    ev = p
__device__ float4 g_varn[MAXV];   // ef=-1: {w*ev, w, -dl, 0},  w = e^{c(1-p)}, ev = 1-p
__device__ double g_acc;
__device__ unsigned int g_ticket;

// One 128-bit vector reduction: 1 RED instead of 3.
__device__ __forceinline__ void red_add_v4(float4* addr, float a, float b, float c)
{
    asm volatile("red.global.add.v4.f32 [%0], {%1, %2, %3, %4};"
                 :: "l"(addr), "f"(a), "f"(b), "f"(c), "f"(0.0f)
                 : "memory");
}

// ---------------------------------------------------------------------------
// Kernel 1: init (persistent grid) — zero g_fun; build per-(variable,sign)
// RED-operand tables so the edge loop does no arithmetic.
// ---------------------------------------------------------------------------
__global__ void __launch_bounds__(256) init_kernel(
    const float* __restrict__ vp,
    const float* __restrict__ dl,
    const float* __restrict__ gs,
    const float* __restrict__ mc,
    int V, int F)
{
    const float coeff = fminf(sqrtf(__ldg(gs)), __ldg(mc));   // ALPHA = 0.5

    int stride = gridDim.x * blockDim.x;
    int i0 = blockIdx.x * blockDim.x + threadIdx.x;
    if (i0 == 0) { g_acc = 0.0; g_ticket = 0u; }

    const float4 z4 = make_float4(0.0f, 0.0f, 0.0f, 0.0f);
    for (int i = i0; i < F; i += stride)
        g_fun[i] = z4;

    for (int i = i0; i < V; i += stride) {
        float p = vp[i];
        float d = dl[i];
        float wp = __expf(coeff * p);
        float q  = 1.0f - p;
        float wn = __expf(coeff * q);
        g_varp[i] = make_float4(wp * p, wp,  d, 0.0f);
        g_varn[i] = make_float4(wn * q, wn, -d, 0.0f);
    }
}

// ---------------------------------------------------------------------------
// Kernel 2: edge scatter, 4 edges per thread.
// Inner loop per edge: sign-select table, one 16B gather, one v4 RED.
// ---------------------------------------------------------------------------
__global__ void __launch_bounds__(256) edge_kernel(
    const int*   __restrict__ var_idx,
    const int*   __restrict__ fun_idx,
    const float* __restrict__ ef,
    int E)
{
    const int E4 = E >> 2;
    int stride = gridDim.x * blockDim.x;
    int tid0 = blockIdx.x * blockDim.x + threadIdx.x;

    const int4*   v4p = (const int4*)var_idx;
    const int4*   f4p = (const int4*)fun_idx;
    const float4* e4p = (const float4*)ef;

    for (int i = tid0; i < E4; i += stride) {
        int4   v4 = v4p[i];
        int4   f4 = f4p[i];
        float4 e4 = e4p[i];

        // Issue all 4 gathers first (MLP), then RED.
        float4 vd[4];
        #pragma unroll
        for (int k = 0; k < 4; k++) {
            int  v  = (&v4.x)[k];
            bool ng = ((&e4.x)[k] < 0.0f);          // sign select
            const float4* tbl = ng ? g_varn : g_varp;
            vd[k] = __ldg(&tbl[v]);
        }

        #pragma unroll
        for (int k = 0; k < 4; k++)
            red_add_v4(&g_fun[(&f4.x)[k]], vd[k].x, vd[k].y, vd[k].z);
    }

    // Tail (E % 4)
    int tail = E4 << 2;
    for (int i = tail + tid0; i < E; i += stride) {
        int  v  = var_idx[i];
        int  f  = fun_idx[i];
        bool ng = (ef[i] < 0.0f);
        const float4* tbl = ng ? g_varn : g_varp;
        float4 vd = __ldg(&tbl[v]);
        red_add_v4(&g_fun[f], vd.x, vd.y, vd.z);
    }
}

// ---------------------------------------------------------------------------
// Kernel 3: per-function clause value + mean reduction + finalize.
// Persistent grid; register-double accumulate; one atomic per block; last
// block (ticket) writes the mean.
// ---------------------------------------------------------------------------
__global__ void __launch_bounds__(256) fun_kernel(
    const float* __restrict__ eps_p,
    const void*  __restrict__ ls_p,
    float* __restrict__ out,
    int F)
{
    // loss_sharpness: defensively decode int-vs-float encoding
    int sharp = 5;
    if (ls_p) {
        int   li = ((const int*)ls_p)[0];
        float lf = ((const float*)ls_p)[0];
        sharp = (li > 0 && li < 1000) ? li : (int)lf;
        if (sharp <= 0 || sharp > 1000) sharp = 5;
    }
    const float eps = eps_p[0];

    double val = 0.0;
    int stride = gridDim.x * blockDim.x;
    for (int i = blockIdx.x * blockDim.x + threadIdx.x; i < F; i += stride) {
        float4 a = g_fun[i];
        float  n = a.x, d = a.y, t = a.z;

        float cv = d / fmaxf(n, eps);
        float x  = cv - 1.0f;
        float pw;
        if (sharp == 5) {                 // fast path: x^5 in 3 mults
            float x2 = x * x;
            pw = x2 * x2 * x;
        } else {
            pw = 1.0f;
            for (int k = 0; k < sharp; k++) pw *= x;
        }
        cv = t * (1.0f + pw);

        // clip(cv, 0) then max(., eps) then log
        val += (double)__logf(fmaxf(fmaxf(cv, 0.0f), eps));
    }

    // Warp reduction then block reduction (doubles)
    #pragma unroll
    for (int off = 16; off > 0; off >>= 1)
        val += __shfl_down_sync(0xffffffffu, val, off);

    __shared__ double swarp[8];
    int lane = threadIdx.x & 31;
    int wid  = threadIdx.x >> 5;
    if (lane == 0) swarp[wid] = val;
    __syncthreads();
    if (wid == 0) {
        val = (lane < (blockDim.x >> 5)) ? swarp[lane] : 0.0;
        #pragma unroll
        for (int off = 4; off > 0; off >>= 1)
            val += __shfl_down_sync(0xffffffffu, val, off);
        if (lane == 0) {
            atomicAdd(&g_acc, val);
            __threadfence();
            unsigned int t = atomicAdd(&g_ticket, 1u);
            if (t == gridDim.x - 1) {
                out[0] = (float)(g_acc / (double)F);
            }
        }
    }
}

// ---------------------------------------------------------------------------
// Launch. Input order (metadata):
//   0 variable_prediction (V,1) f32
//   1 degree_loss        (V,)  f32
//   2 label              (B,)  f32      [unused]
//   3 graph_map          (2,E) i32      [row0 = var_idx, row1 = fun_idx]
//   4 batch_variable_map (V,)  i32      [unused]
//   5 batch_function_map (F,)  i32      [only shape used: F]
//   6 edge_feature       (E,1) f32
//   7 meta_data          (1,)  f32      [unused]
//   8 global_step        (1,)  f32
//   9 eps                (1,)  f32
//  10 max_coeff          (1,)  f32
//  11 loss_sharpness     scalar
// ---------------------------------------------------------------------------
extern "C" void kernel_launch(void* const* d_in, const int* in_sizes, int n_in,
                              void* d_out, int out_size)
{
    const float* vp   = (const float*)d_in[0];
    const float* dl   = (const float*)d_in[1];
    const int*   gmap = (const int*)  d_in[3];
    const float* ef   = (const float*)d_in[6];
    const float* gs   = (const float*)d_in[8];
    const float* eps  = (const float*)d_in[9];
    const float* mc   = (const float*)d_in[10];
    const void*  ls   = (n_in > 11) ? d_in[11] : nullptr;

    const int V = in_sizes[0];              // number of variables
    const int F = in_sizes[5];              // number of functions (segments)
    const int E = in_sizes[6];              // number of edges
    const int* var_idx = gmap;              // graph_map[0]
    const int* fun_idx = gmap + E;          // graph_map[1]

    float* out = (float*)d_out;

    const int TPB = 256;
    const int gridP = 1184;                 // 148 SMs * 8 blocks (persistent)
    int gridE = ((E >> 2) + TPB - 1) / TPB; if (gridE > 8192) gridE = 8192;

    init_kernel<<<gridP, TPB>>>(vp, dl, gs, mc, V, F);
    edge_kernel<<<gridE, TPB>>>(var_idx, fun_idx, ef, E);
    fun_kernel<<<gridP, TPB>>>(eps, ls, out, F);
}

// round 11
// speedup vs baseline: 1.2816x; 1.2816x over previous
#include <cuda_runtime.h>
#include <math.h>

// Problem capacities (runtime sizes from in_sizes)
#define MAXF 2000000
#define MAXV 500000

// Scratch (allocation-free rule: __device__ globals).
// g_fun relies on: (a) CUDA zero-initialization of __device__ globals at
// module load, (b) fun_kernel restoring zeros after each consumption. So
// every kernel_launch call observes g_fun == 0 at edge_kernel time.
__device__ float4 g_fun[MAXF];   // .x = nom, .y = den, .z = tmp, .w unused
__device__ float4 g_var[MAXV];   // {p, dl, exp(c*p), exp(c*(1-p))}
__device__ double g_acc;
__device__ unsigned int g_ticket;

// One 128-bit vector reduction: 1 RED instead of 3.
__device__ __forceinline__ void red_add_v4(float4* addr, float a, float b, float c)
{
    asm volatile("red.global.add.v4.f32 [%0], {%1, %2, %3, %4};"
                 :: "l"(addr), "f"(a), "f"(b), "f"(c), "f"(0.0f)
                 : "memory");
}

// ---------------------------------------------------------------------------
// Kernel 1: init — pack per-variable {p, dl, e^{c p}, e^{c(1-p)}} and reset
// scalars. (No g_fun zeroing: see note above.)
// ---------------------------------------------------------------------------
__global__ void __launch_bounds__(256) init_kernel(
    const float* __restrict__ vp,
    const float* __restrict__ dl,
    const float* __restrict__ gs,
    const float* __restrict__ mc,
    int V)
{
    const float coeff = fminf(sqrtf(__ldg(gs)), __ldg(mc));   // ALPHA = 0.5

    int stride = gridDim.x * blockDim.x;
    int i0 = blockIdx.x * blockDim.x + threadIdx.x;
    if (i0 == 0) { g_acc = 0.0; g_ticket = 0u; }

    for (int i = i0; i < V; i += stride) {
        float p = vp[i];
        float d = dl[i];
        g_var[i] = make_float4(p, d, __expf(coeff * p), __expf(coeff * (1.0f - p)));
    }
}

// ---------------------------------------------------------------------------
// Kernel 2: edge scatter, 4 edges per thread. Value-selects only (no
// address selection — that caused divergent gathers in R10).
//   ef=+1: ev=p,   w=e^{c p},     tl=+dl
//   ef=-1: ev=1-p, w=e^{c(1-p)},  tl=-dl
// ---------------------------------------------------------------------------
__global__ void __launch_bounds__(256) edge_kernel(
    const int*   __restrict__ var_idx,
    const int*   __restrict__ fun_idx,
    const float* __restrict__ ef,
    int E)
{
    const int E4 = E >> 2;
    int stride = gridDim.x * blockDim.x;
    int tid0 = blockIdx.x * blockDim.x + threadIdx.x;

    const int4*   v4p = (const int4*)var_idx;
    const int4*   f4p = (const int4*)fun_idx;
    const float4* e4p = (const float4*)ef;

    for (int i = tid0; i < E4; i += stride) {
        int4   v4 = v4p[i];
        int4   f4 = f4p[i];
        float4 e4 = e4p[i];

        // Issue all 4 gathers first (MLP), then select + RED.
        float4 vd[4];
        #pragma unroll
        for (int k = 0; k < 4; k++)
            vd[k] = g_var[(&v4.x)[k]];

        #pragma unroll
        for (int k = 0; k < 4; k++) {
            int   f   = (&f4.x)[k];
            bool  pos = ((&e4.x)[k] > 0.0f);

            float ev = pos ? vd[k].x : (1.0f - vd[k].x);
            float w  = pos ? vd[k].z : vd[k].w;
            float tl = pos ? vd[k].y : -vd[k].y;

            red_add_v4(&g_fun[f], w * ev, w, tl);
        }
    }

    // Tail (E % 4)
    int tail = E4 << 2;
    for (int i = tail + tid0; i < E; i += stride) {
        int    v  = var_idx[i];
        int    f  = fun_idx[i];
        bool  pos = (ef[i] > 0.0f);
        float4 vd = g_var[v];
        float ev = pos ? vd.x : (1.0f - vd.x);
        float w  = pos ? vd.z : vd.w;
        float tl = pos ? vd.y : -vd.y;
        red_add_v4(&g_fun[f], w * ev, w, tl);
    }
}

// ---------------------------------------------------------------------------
// Kernel 3: per-function clause value + mean reduction + finalize.
// Persistent grid. ALSO restores g_fun[i] = 0 after consuming it, so the
// next kernel_launch call starts from zeros without an explicit zero pass.
// ---------------------------------------------------------------------------
__global__ void __launch_bounds__(256) fun_kernel(
    const float* __restrict__ eps_p,
    const void*  __restrict__ ls_p,
    float* __restrict__ out,
    int F)
{
    // loss_sharpness: defensively decode int-vs-float encoding
    int sharp = 5;
    if (ls_p) {
        int   li = ((const int*)ls_p)[0];
        float lf = ((const float*)ls_p)[0];
        sharp = (li > 0 && li < 1000) ? li : (int)lf;
        if (sharp <= 0 || sharp > 1000) sharp = 5;
    }
    const float eps = eps_p[0];
    const float4 z4 = make_float4(0.0f, 0.0f, 0.0f, 0.0f);

    double val = 0.0;
    int stride = gridDim.x * blockDim.x;
    for (int i = blockIdx.x * blockDim.x + threadIdx.x; i < F; i += stride) {
        float4 a = g_fun[i];
        g_fun[i] = z4;                     // restore zeros for next call
        float  n = a.x, d = a.y, t = a.z;

        float cv = d / fmaxf(n, eps);
        float x  = cv - 1.0f;
        float pw;
        if (sharp == 5) {                  // fast path: x^5 in 3 mults
            float x2 = x * x;
            pw = x2 * x2 * x;
        } else {
            pw = 1.0f;
            for (int k = 0; k < sharp; k++) pw *= x;
        }
        cv = t * (1.0f + pw);

        // clip(cv, 0) then max(., eps) then log
        val += (double)__logf(fmaxf(fmaxf(cv, 0.0f), eps));
    }

    // Warp reduction then block reduction (doubles)
    #pragma unroll
    for (int off = 16; off > 0; off >>= 1)
        val += __shfl_down_sync(0xffffffffu, val, off);

    __shared__ double swarp[8];
    int lane = threadIdx.x & 31;
    int wid  = threadIdx.x >> 5;
    if (lane == 0) swarp[wid] = val;
    __syncthreads();
    if (wid == 0) {
        val = (lane < (blockDim.x >> 5)) ? swarp[lane] : 0.0;
        #pragma unroll
        for (int off = 4; off > 0; off >>= 1)
            val += __shfl_down_sync(0xffffffffu, val, off);
        if (lane == 0) {
            atomicAdd(&g_acc, val);
            __threadfence();
            unsigned int t = atomicAdd(&g_ticket, 1u);
            if (t == gridDim.x - 1) {
                out[0] = (float)(g_acc / (double)F);
            }
        }
    }
}

// ---------------------------------------------------------------------------
// Launch. Input order (metadata):
//   0 variable_prediction (V,1) f32
//   1 degree_loss        (V,)  f32
//   2 label              (B,)  f32      [unused]
//   3 graph_map          (2,E) i32      [row0 = var_idx, row1 = fun_idx]
//   4 batch_variable_map (V,)  i32      [unused]
//   5 batch_function_map (F,)  i32      [only shape used: F]
//   6 edge_feature       (E,1) f32
//   7 meta_data          (1,)  f32      [unused]
//   8 global_step        (1,)  f32
//   9 eps                (1,)  f32
//  10 max_coeff          (1,)  f32
//  11 loss_sharpness     scalar
// ---------------------------------------------------------------------------
extern "C" void kernel_launch(void* const* d_in, const int* in_sizes, int n_in,
                              void* d_out, int out_size)
{
    const float* vp   = (const float*)d_in[0];
    const float* dl   = (const float*)d_in[1];
    const int*   gmap = (const int*)  d_in[3];
    const float* ef   = (const float*)d_in[6];
    const float* gs   = (const float*)d_in[8];
    const float* eps  = (const float*)d_in[9];
    const float* mc   = (const float*)d_in[10];
    const void*  ls   = (n_in > 11) ? d_in[11] : nullptr;

    const int V = in_sizes[0];              // number of variables
    const int F = in_sizes[5];              // number of functions (segments)
    const int E = in_sizes[6];              // number of edges
    const int* var_idx = gmap;              // graph_map[0]
    const int* fun_idx = gmap + E;          // graph_map[1]

    float* out = (float*)d_out;

    const int TPB = 256;
    int gridV = (V + TPB - 1) / TPB;        if (gridV > 4096) gridV = 4096;
    int gridE = ((E >> 2) + TPB - 1) / TPB; if (gridE > 8192) gridE = 8192;
    const int gridFun = 1184;               // 148 SMs * 8 blocks (persistent)

    init_kernel<<<gridV, TPB>>>(vp, dl, gs, mc, V);
    edge_kernel<<<gridE, TPB>>>(var_idx, fun_idx, ef, E);
    fun_kernel<<<gridFun, TPB>>>(eps, ls, out, F);
}

// round 12
// speedup vs baseline: 1.5530x; 1.2117x over previous
#include <cuda_runtime.h>
#include <math.h>

// Problem capacities (runtime sizes from in_sizes)
#define MAXF 2000000
#define MAXV 500000

// Scratch (allocation-free rule: __device__ globals)
__device__ float4 g_fun[MAXF];   // .x = nom, .y = den, .z = tmp, .w unused
__device__ float4 g_var[MAXV];   // {p, dl, exp(c*p), exp(c*(1-p))}
__device__ double g_acc;
__device__ unsigned int g_ticket;

// One 128-bit vector reduction: 1 RED instead of 3.
__device__ __forceinline__ void red_add_v4(float4* addr, float a, float b, float c)
{
    asm volatile("red.global.add.v4.f32 [%0], {%1, %2, %3, %4};"
                 :: "l"(addr), "f"(a), "f"(b), "f"(c), "f"(0.0f)
                 : "memory");
}

// ---------------------------------------------------------------------------
// Kernel 1: init — zero g_fun; precompute per-variable {p, dl, e^{c p}, e^{c(1-p)}}.
// (R9 configuration: non-persistent grid, one pass each.)
// ---------------------------------------------------------------------------
__global__ void __launch_bounds__(256) init_kernel(
    const float* __restrict__ vp,
    const float* __restrict__ dl,
    const float* __restrict__ gs,
    const float* __restrict__ mc,
    int V, int F)
{
    const float coeff = fminf(sqrtf(__ldg(gs)), __ldg(mc));   // ALPHA = 0.5

    int stride = gridDim.x * blockDim.x;
    int i0 = blockIdx.x * blockDim.x + threadIdx.x;
    if (i0 == 0) { g_acc = 0.0; g_ticket = 0u; }
    for (int i = i0; i < F; i += stride)
        g_fun[i] = make_float4(0.0f, 0.0f, 0.0f, 0.0f);
    for (int i = i0; i < V; i += stride) {
        float p = vp[i];
        float d = dl[i];
        g_var[i] = make_float4(p, d, __expf(coeff * p), __expf(coeff * (1.0f - p)));
    }
}

// ---------------------------------------------------------------------------
// Kernel 2: edge scatter, 8 edges per thread (deeper MLP than R9's 4).
// Value-selects only (no address selection).
//   ef=+1: ev=p,   w=e^{c p},     tl=+dl
//   ef=-1: ev=1-p, w=e^{c(1-p)},  tl=-dl
// ---------------------------------------------------------------------------
__global__ void __launch_bounds__(256) edge_kernel(
    const int*   __restrict__ var_idx,
    const int*   __restrict__ fun_idx,
    const float* __restrict__ ef,
    int E)
{
    const int E8 = E >> 3;
    int stride = gridDim.x * blockDim.x;
    int tid0 = blockIdx.x * blockDim.x + threadIdx.x;

    const int4*   v4p = (const int4*)var_idx;
    const int4*   f4p = (const int4*)fun_idx;
    const float4* e4p = (const float4*)ef;

    for (int i = tid0; i < E8; i += stride) {
        int j = 2 * i;
        int4   v4a = v4p[j],     v4b = v4p[j + 1];
        float4 e4a = e4p[j],     e4b = e4p[j + 1];

        // Issue all 8 gathers first (MLP), then selects + REDs.
        float4 vd[8];
        #pragma unroll
        for (int k = 0; k < 4; k++) vd[k]     = g_var[(&v4a.x)[k]];
        #pragma unroll
        for (int k = 0; k < 4; k++) vd[4 + k] = g_var[(&v4b.x)[k]];

        int4 f4a = f4p[j], f4b = f4p[j + 1];

        #pragma unroll
        for (int k = 0; k < 8; k++) {
            int   f   = (k < 4) ? (&f4a.x)[k] : (&f4b.x)[k - 4];
            float e   = (k < 4) ? (&e4a.x)[k] : (&e4b.x)[k - 4];
            bool  pos = (e > 0.0f);

            float ev = pos ? vd[k].x : (1.0f - vd[k].x);
            float w  = pos ? vd[k].z : vd[k].w;
            float tl = pos ? vd[k].y : -vd[k].y;

            red_add_v4(&g_fun[f], w * ev, w, tl);
        }
    }

    // Tail (E % 8)
    int tail = E8 << 3;
    for (int i = tail + tid0; i < E; i += stride) {
        int    v  = var_idx[i];
        int    f  = fun_idx[i];
        bool  pos = (ef[i] > 0.0f);
        float4 vd = g_var[v];
        float ev = pos ? vd.x : (1.0f - vd.x);
        float w  = pos ? vd.z : vd.w;
        float tl = pos ? vd.y : -vd.y;
        red_add_v4(&g_fun[f], w * ev, w, tl);
    }
}

// ---------------------------------------------------------------------------
// Kernel 3: per-function clause value + mean reduction + finalize.
// Persistent grid; register-double accumulate; one atomic per block; last
// block (ticket) writes the mean. (Read-only on g_fun — no zero restore.)
// ---------------------------------------------------------------------------
__global__ void __launch_bounds__(256) fun_kernel(
    const float* __restrict__ eps_p,
    const void*  __restrict__ ls_p,
    float* __restrict__ out,
    int F)
{
    // loss_sharpness: defensively decode int-vs-float encoding
    int sharp = 5;
    if (ls_p) {
        int   li = ((const int*)ls_p)[0];
        float lf = ((const float*)ls_p)[0];
        sharp = (li > 0 && li < 1000) ? li : (int)lf;
        if (sharp <= 0 || sharp > 1000) sharp = 5;
    }
    const float eps = eps_p[0];

    double val = 0.0;
    int stride = gridDim.x * blockDim.x;
    for (int i = blockIdx.x * blockDim.x + threadIdx.x; i < F; i += stride) {
        float4 a = g_fun[i];
        float  n = a.x, d = a.y, t = a.z;

        float cv = d / fmaxf(n, eps);
        float x  = cv - 1.0f;
        float pw;
        if (sharp == 5) {                  // fast path: x^5 in 3 mults
            float x2 = x * x;
            pw = x2 * x2 * x;
        } else {
            pw = 1.0f;
            for (int k = 0; k < sharp; k++) pw *= x;
        }
        cv = t * (1.0f + pw);

        // clip(cv, 0) then max(., eps) then log
        val += (double)__logf(fmaxf(fmaxf(cv, 0.0f), eps));
    }

    // Warp reduction then block reduction (doubles)
    #pragma unroll
    for (int off = 16; off > 0; off >>= 1)
        val += __shfl_down_sync(0xffffffffu, val, off);

    __shared__ double swarp[8];
    int lane = threadIdx.x & 31;
    int wid  = threadIdx.x >> 5;
    if (lane == 0) swarp[wid] = val;
    __syncthreads();
    if (wid == 0) {
        val = (lane < (blockDim.x >> 5)) ? swarp[lane] : 0.0;
        #pragma unroll
        for (int off = 4; off > 0; off >>= 1)
            val += __shfl_down_sync(0xffffffffu, val, off);
        if (lane == 0) {
            atomicAdd(&g_acc, val);
            __threadfence();
            unsigned int t = atomicAdd(&g_ticket, 1u);
            if (t == gridDim.x - 1) {
                out[0] = (float)(g_acc / (double)F);
            }
        }
    }
}

// ---------------------------------------------------------------------------
// Launch. Input order (metadata):
//   0 variable_prediction (V,1) f32
//   1 degree_loss        (V,)  f32
//   2 label              (B,)  f32      [unused]
//   3 graph_map          (2,E) i32      [row0 = var_idx, row1 = fun_idx]
//   4 batch_variable_map (V,)  i32      [unused]
//   5 batch_function_map (F,)  i32      [only shape used: F]
//   6 edge_feature       (E,1) f32
//   7 meta_data          (1,)  f32      [unused]
//   8 global_step        (1,)  f32
//   9 eps                (1,)  f32
//  10 max_coeff          (1,)  f32
//  11 loss_sharpness     scalar
// ---------------------------------------------------------------------------
extern "C" void kernel_launch(void* const* d_in, const int* in_sizes, int n_in,
                              void* d_out, int out_size)
{
    const float* vp   = (const float*)d_in[0];
    const float* dl   = (const float*)d_in[1];
    const int*   gmap = (const int*)  d_in[3];
    const float* ef   = (const float*)d_in[6];
    const float* gs   = (const float*)d_in[8];
    const float* eps  = (const float*)d_in[9];
    const float* mc   = (const float*)d_in[10];
    const void*  ls   = (n_in > 11) ? d_in[11] : nullptr;

    const int V = in_sizes[0];              // number of variables
    const int F = in_sizes[5];              // number of functions (segments)
    const int E = in_sizes[6];              // number of edges
    const int* var_idx = gmap;              // graph_map[0]
    const int* fun_idx = gmap + E;          // graph_map[1]

    float* out = (float*)d_out;

    const int TPB = 256;
    int gridI = (F + TPB - 1) / TPB;        if (gridI > 8192) gridI = 8192;
    int gridE = ((E >> 3) + TPB - 1) / TPB; if (gridE > 8192) gridE = 8192;
    const int gridFun = 1184;               // 148 SMs * 8 blocks

    init_kernel<<<gridI, TPB>>>(vp, dl, gs, mc, V, F);
    edge_kernel<<<gridE, TPB>>>(var_idx, fun_idx, ef, E);
    fun_kernel<<<gridFun, TPB>>>(eps, ls, out, F);
}